// round 3
// baseline (speedup 1.0000x reference)
#include <cuda_runtime.h>

// ---------------------------------------------------------------------------
// JRTransformer fused kernel (fp32, FFMA path)
//
// THEORY / HW MODEL (R3):
//  - B=16384 independent elements, each [15,128] tokens, 6 layers.
//  - Total ~226 G-FMA, dominated by qkv GEMMs (2x [15,128]x[128,384] per
//    element-layer). Weights ~3MB total (L2-resident); activations ~380MB
//    HBM in+out (trivial at 8TB/s). Binding constraint: fp32 FFMA issue,
//    148 SM x 4 SMSP x 0.5 FFMA/cyc x 32 lanes -> ~13ms floor.
//  - Hazard avoided: per-warp weight re-reads would be ~50GB of L2 traffic.
//    All weights staged through a CTA-shared 25KB smem buffer, amortized
//    over EPC=7 elements/CTA -> ~7GB L2 traffic total.
//  - Grid: ceil(16384/7)=2341 CTAs x 224 threads, 1 CTA/SM (220KB smem).
//    One warp owns one element end-to-end; x and normalized relation live
//    in registers; jn/rn/ao in per-warp smem; per-head qkv in smem scratch;
//    scores+softmax row-per-lane in registers (15 of 32 lanes active).
// PREDICTIONS: passed=true, rel_err ~1e-6, dur_us 13000-18000.
//  ncu: FMA pipe >=65% peak, dram <3%, tensor 0, stalls: barrier (16 heads
//  x 2 syncthreads x 6 layers) + short_scoreboard on LDS-fed FFMA chains.
// ---------------------------------------------------------------------------

#define NB      16384
#define NJ      15
#define NDEPTH  6
#define EPC     7          // elements (warps) per CTA
#define NTHR    (EPC*32)

// per-warp smem region (floats): jn[16*128] rn[16*128] ao[16*128] qs[768]
#define WSTRIDE   6912
#define WBUF_OFF  (EPC*WSTRIDE)       // 48384
#define WBUF_FLTS 6400                // weight staging buffer
#define CBUF_OFF  (WBUF_OFF + WBUF_FLTS)
#define SMEM_FLOATS (CBUF_OFF + 144)
#define SMEM_BYTES  (SMEM_FLOATS*4)   // 219,712 B

__device__ __forceinline__ void row_stats4(float v0, float v1, float v2, float v3,
                                           float& mu, float& inv) {
    float s  = v0 + v1 + v2 + v3;
    float ss = v0*v0 + v1*v1 + v2*v2 + v3*v3;
    #pragma unroll
    for (int off = 16; off > 0; off >>= 1) {
        s  += __shfl_xor_sync(0xffffffffu, s,  off);
        ss += __shfl_xor_sync(0xffffffffu, ss, off);
    }
    mu = s * (1.0f/128.0f);
    float var = ss * (1.0f/128.0f) - mu*mu;
    inv = rsqrtf(var + 1e-5f);
}

__global__ __launch_bounds__(NTHR, 1)
void jr_kernel(const float* __restrict__ joint, const float* __restrict__ rel,
               const float* __restrict__ Jqkv_w, const float* __restrict__ Jqkv_b,
               const float* __restrict__ Iqk_w,  const float* __restrict__ Iqk_b,
               const float* __restrict__ Iconv_w,const float* __restrict__ Iconv_b,
               const float* __restrict__ proj_w, const float* __restrict__ proj_b,
               const float* __restrict__ ln1_w,  const float* __restrict__ ln1_b,
               const float* __restrict__ ln2_w,  const float* __restrict__ ln2_b,
               const float* __restrict__ ln3_w,  const float* __restrict__ ln3_b,
               const float* __restrict__ fc1_w,  const float* __restrict__ fc1_b,
               const float* __restrict__ fc2_w,  const float* __restrict__ fc2_b,
               float* __restrict__ out)
{
    extern __shared__ float sm[];
    const int tid  = threadIdx.x;
    const int wid  = tid >> 5;
    const int lane = tid & 31;
    const int c0   = lane * 4;       // this lane owns cols c0..c0+3
    const int mr   = lane >> 3;      // 0..3  (row group for qkv stage)
    const int dd   = lane & 7;       // 0..7  (head-dim for qkv stage)

    float* jn   = sm + wid * WSTRIDE;     // [16][128]
    float* rn   = jn + 2048;              // [16][128]  (reused as hid [16][64])
    float* ao   = rn + 2048;              // [16][128]  attention output
    float* qs   = ao + 2048;              // [6][16][8] per-head qkv scratch
    float* wbuf = sm + WBUF_OFF;          // 6400 floats, staged weights
    float* cbuf = sm + CBUF_OFF;          // Iconv: [8][16] + [16]

    const int  eb   = blockIdx.x * EPC + wid;
    const int  e    = eb < NB ? eb : (NB - 1);
    const long base = (long)e * (NJ * 128);

    // ---- load x (joint) and normalized relation rhat into registers ----
    float x[NJ][4], rh[NJ][4];
    #pragma unroll
    for (int n = 0; n < NJ; n++) {
        float4 v = *reinterpret_cast<const float4*>(joint + base + n*128 + c0);
        x[n][0]=v.x; x[n][1]=v.y; x[n][2]=v.z; x[n][3]=v.w;
    }
    #pragma unroll
    for (int n = 0; n < NJ; n++) {
        float4 v = *reinterpret_cast<const float4*>(rel + base + n*128 + c0);
        rh[n][0]=v.x; rh[n][1]=v.y; rh[n][2]=v.z; rh[n][3]=v.w;
    }
    #pragma unroll
    for (int n = 0; n < NJ; n++) {
        float mu, inv;
        row_stats4(rh[n][0], rh[n][1], rh[n][2], rh[n][3], mu, inv);
        #pragma unroll
        for (int j = 0; j < 4; j++) rh[n][j] = (rh[n][j] - mu) * inv;
    }

    // zero padded row 15 of the activation buffers (stays zero forever)
    {
        float4 z = make_float4(0.f, 0.f, 0.f, 0.f);
        *reinterpret_cast<float4*>(jn + 15*128 + c0) = z;
        *reinterpret_cast<float4*>(rn + 15*128 + c0) = z;
        *reinterpret_cast<float4*>(ao + 15*128 + c0) = z;
    }

    for (int L = 0; L < NDEPTH; L++) {
        const float* Jw = Jqkv_w + L*49152;
        const float* Jb = Jqkv_b + L*384;
        const float* Iw = Iqk_w  + L*49152;
        const float* Ib = Iqk_b  + L*384;
        const float* Pw = proj_w + L*16384;

        // ---------------- LN1(x)->jn, ln2 applied to rhat -> rn ----------
        {
            float4 w1 = *reinterpret_cast<const float4*>(ln1_w + L*128 + c0);
            float4 b1 = *reinterpret_cast<const float4*>(ln1_b + L*128 + c0);
            float4 w2 = *reinterpret_cast<const float4*>(ln2_w + L*128 + c0);
            float4 b2 = *reinterpret_cast<const float4*>(ln2_b + L*128 + c0);
            #pragma unroll
            for (int n = 0; n < NJ; n++) {
                float mu, inv;
                row_stats4(x[n][0], x[n][1], x[n][2], x[n][3], mu, inv);
                float4 o;
                o.x = fmaf((x[n][0]-mu)*inv, w1.x, b1.x);
                o.y = fmaf((x[n][1]-mu)*inv, w1.y, b1.y);
                o.z = fmaf((x[n][2]-mu)*inv, w1.z, b1.z);
                o.w = fmaf((x[n][3]-mu)*inv, w1.w, b1.w);
                *reinterpret_cast<float4*>(jn + n*128 + c0) = o;
                float4 r;
                r.x = fmaf(rh[n][0], w2.x, b2.x);
                r.y = fmaf(rh[n][1], w2.y, b2.y);
                r.z = fmaf(rh[n][2], w2.z, b2.z);
                r.w = fmaf(rh[n][3], w2.w, b2.w);
                *reinterpret_cast<float4*>(rn + n*128 + c0) = r;
            }
        }
        // stage Iconv (Cw [8][15] padded to [8][16], Cb [15] padded to [16])
        if (tid < 128) {
            int d2 = tid >> 4, m = tid & 15;
            cbuf[tid] = (m < NJ) ? Iconv_w[L*(8*NJ) + d2*NJ + m] : 0.f;
        } else if (tid < 144) {
            int m = tid - 128;
            cbuf[128 + m] = (m < NJ) ? Iconv_b[L*NJ + m] : 0.f;
        }

        // ---------------- attention, head by head ------------------------
        #pragma unroll 1
        for (int h = 0; h < 16; h++) {
            __syncthreads();   // prior consumers of wbuf / qs done
            // stage 48-col head tile: wbuf[j*132+k], j = mat*8+d
            // (mat order: Jq,Jk,Jv,Iq,Ik,Iv)
            for (int idx = tid; idx < 6144; idx += NTHR) {
                int k   = idx / 48;
                int j   = idx - k * 48;
                int mat = j >> 3;
                int d   = j & 7;
                int col = (mat >= 3 ? mat - 3 : mat) * 128 + h*8 + d;
                const float* src = (mat < 3) ? Jw : Iw;
                wbuf[j*132 + k] = src[k*384 + col];
            }
            if (tid < 48) {
                int mat = tid >> 3, d = tid & 7;
                const float* sb = (mat < 3) ? Jb : Ib;
                wbuf[6336 + tid] = sb[(mat >= 3 ? mat - 3 : mat)*128 + h*8 + d];
            }
            __syncthreads();

            // per-lane (mr,dd): 6 matrices x 4 rows accumulators
            float acc[6][4];
            #pragma unroll
            for (int mt = 0; mt < 6; mt++) {
                float bv = wbuf[6336 + mt*8 + dd];
                acc[mt][0]=bv; acc[mt][1]=bv; acc[mt][2]=bv; acc[mt][3]=bv;
            }
            #pragma unroll 4
            for (int k = 0; k < 128; k += 4) {
                float4 aj0 = *reinterpret_cast<float4*>(jn + (mr     )*128 + k);
                float4 aj1 = *reinterpret_cast<float4*>(jn + (mr +  4)*128 + k);
                float4 aj2 = *reinterpret_cast<float4*>(jn + (mr +  8)*128 + k);
                float4 aj3 = *reinterpret_cast<float4*>(jn + (mr + 12)*128 + k);
                float4 ar0 = *reinterpret_cast<float4*>(rn + (mr     )*128 + k);
                float4 ar1 = *reinterpret_cast<float4*>(rn + (mr +  4)*128 + k);
                float4 ar2 = *reinterpret_cast<float4*>(rn + (mr +  8)*128 + k);
                float4 ar3 = *reinterpret_cast<float4*>(rn + (mr + 12)*128 + k);
                #pragma unroll
                for (int mt = 0; mt < 3; mt++) {
                    float4 w = *reinterpret_cast<float4*>(wbuf + (mt*8 + dd)*132 + k);
                    acc[mt][0] = fmaf(aj0.x,w.x,fmaf(aj0.y,w.y,fmaf(aj0.z,w.z,fmaf(aj0.w,w.w,acc[mt][0]))));
                    acc[mt][1] = fmaf(aj1.x,w.x,fmaf(aj1.y,w.y,fmaf(aj1.z,w.z,fmaf(aj1.w,w.w,acc[mt][1]))));
                    acc[mt][2] = fmaf(aj2.x,w.x,fmaf(aj2.y,w.y,fmaf(aj2.z,w.z,fmaf(aj2.w,w.w,acc[mt][2]))));
                    acc[mt][3] = fmaf(aj3.x,w.x,fmaf(aj3.y,w.y,fmaf(aj3.z,w.z,fmaf(aj3.w,w.w,acc[mt][3]))));
                }
                #pragma unroll
                for (int mt = 3; mt < 6; mt++) {
                    float4 w = *reinterpret_cast<float4*>(wbuf + (mt*8 + dd)*132 + k);
                    acc[mt][0] = fmaf(ar0.x,w.x,fmaf(ar0.y,w.y,fmaf(ar0.z,w.z,fmaf(ar0.w,w.w,acc[mt][0]))));
                    acc[mt][1] = fmaf(ar1.x,w.x,fmaf(ar1.y,w.y,fmaf(ar1.z,w.z,fmaf(ar1.w,w.w,acc[mt][1]))));
                    acc[mt][2] = fmaf(ar2.x,w.x,fmaf(ar2.y,w.y,fmaf(ar2.z,w.z,fmaf(ar2.w,w.w,acc[mt][2]))));
                    acc[mt][3] = fmaf(ar3.x,w.x,fmaf(ar3.y,w.y,fmaf(ar3.z,w.z,fmaf(ar3.w,w.w,acc[mt][3]))));
                }
            }
            #pragma unroll
            for (int mt = 0; mt < 6; mt++) {
                #pragma unroll
                for (int i = 0; i < 4; i++)
                    qs[mt*128 + (mr + 4*i)*8 + dd] = acc[mt][i];
            }
            __syncwarp();

            // scores + softmax + out : lane n owns row n
            if (lane < NJ) {
                const int n = lane;
                float4 q0 = *reinterpret_cast<float4*>(qs + 0*128 + n*8);
                float4 q1 = *reinterpret_cast<float4*>(qs + 0*128 + n*8 + 4);
                float4 u0 = *reinterpret_cast<float4*>(qs + 3*128 + n*8);
                float4 u1 = *reinterpret_cast<float4*>(qs + 3*128 + n*8 + 4);
                float4 v0 = *reinterpret_cast<float4*>(qs + 5*128 + n*8);
                float4 v1 = *reinterpret_cast<float4*>(qs + 5*128 + n*8 + 4);
                float iv[8] = {v0.x,v0.y,v0.z,v0.w,v1.x,v1.y,v1.z,v1.w};
                float sc[NJ];
                #pragma unroll
                for (int m = 0; m < NJ; m++) {
                    float4 k0 = *reinterpret_cast<float4*>(qs + 1*128 + m*8);
                    float4 k1 = *reinterpret_cast<float4*>(qs + 1*128 + m*8 + 4);
                    float4 i0 = *reinterpret_cast<float4*>(qs + 4*128 + m*8);
                    float4 i1 = *reinterpret_cast<float4*>(qs + 4*128 + m*8 + 4);
                    float t = cbuf[128 + m];
                    #pragma unroll
                    for (int d = 0; d < 8; d++) t = fmaf(iv[d], cbuf[d*16 + m], t);
                    t = fmaf(q0.x,k0.x,t); t = fmaf(q0.y,k0.y,t);
                    t = fmaf(q0.z,k0.z,t); t = fmaf(q0.w,k0.w,t);
                    t = fmaf(q1.x,k1.x,t); t = fmaf(q1.y,k1.y,t);
                    t = fmaf(q1.z,k1.z,t); t = fmaf(q1.w,k1.w,t);
                    t = fmaf(u0.x,i0.x,t); t = fmaf(u0.y,i0.y,t);
                    t = fmaf(u0.z,i0.z,t); t = fmaf(u0.w,i0.w,t);
                    t = fmaf(u1.x,i1.x,t); t = fmaf(u1.y,i1.y,t);
                    t = fmaf(u1.z,i1.z,t); t = fmaf(u1.w,i1.w,t);
                    sc[m] = t * 0.6f;
                }
                float mx = sc[0];
                #pragma unroll
                for (int m = 1; m < NJ; m++) mx = fmaxf(mx, sc[m]);
                float sum = 0.f;
                #pragma unroll
                for (int m = 0; m < NJ; m++) { sc[m] = __expf(sc[m] - mx); sum += sc[m]; }
                float rs = 1.0f / sum;
                float o[8] = {0,0,0,0,0,0,0,0};
                #pragma unroll
                for (int m = 0; m < NJ; m++) {
                    float4 jv0 = *reinterpret_cast<float4*>(qs + 2*128 + m*8);
                    float4 jv1 = *reinterpret_cast<float4*>(qs + 2*128 + m*8 + 4);
                    float pm = sc[m] * rs;
                    o[0]=fmaf(pm,jv0.x,o[0]); o[1]=fmaf(pm,jv0.y,o[1]);
                    o[2]=fmaf(pm,jv0.z,o[2]); o[3]=fmaf(pm,jv0.w,o[3]);
                    o[4]=fmaf(pm,jv1.x,o[4]); o[5]=fmaf(pm,jv1.y,o[5]);
                    o[6]=fmaf(pm,jv1.z,o[6]); o[7]=fmaf(pm,jv1.w,o[7]);
                }
                *reinterpret_cast<float4*>(ao + n*128 + h*8    ) = make_float4(o[0],o[1],o[2],o[3]);
                *reinterpret_cast<float4*>(ao + n*128 + h*8 + 4) = make_float4(o[4],o[5],o[6],o[7]);
            }
            __syncwarp();
        } // heads

        // ---------------- proj: x += ao @ Pw + Pb ------------------------
        #pragma unroll 1
        for (int kc = 0; kc < 4; kc++) {
            __syncthreads();
            for (int idx = tid; idx < 4096; idx += NTHR)
                wbuf[idx] = Pw[(kc*32 + (idx >> 7))*128 + (idx & 127)];
            __syncthreads();
            #pragma unroll 2
            for (int kk = 0; kk < 32; kk++) {
                float a[NJ];
                #pragma unroll
                for (int n = 0; n < NJ; n++) a[n] = ao[n*128 + kc*32 + kk];
                float4 w = *reinterpret_cast<float4*>(wbuf + kk*128 + c0);
                #pragma unroll
                for (int n = 0; n < NJ; n++) {
                    x[n][0] = fmaf(a[n], w.x, x[n][0]);
                    x[n][1] = fmaf(a[n], w.y, x[n][1]);
                    x[n][2] = fmaf(a[n], w.z, x[n][2]);
                    x[n][3] = fmaf(a[n], w.w, x[n][3]);
                }
            }
        }
        {
            float4 pb = *reinterpret_cast<const float4*>(proj_b + L*128 + c0);
            #pragma unroll
            for (int n = 0; n < NJ; n++) {
                x[n][0]+=pb.x; x[n][1]+=pb.y; x[n][2]+=pb.z; x[n][3]+=pb.w;
            }
        }

        // ---------------- MLP: ln3 -> jn; fc1+gelu -> rn; fc2 -> x -------
        {
            float4 w3 = *reinterpret_cast<const float4*>(ln3_w + L*128 + c0);
            float4 b3 = *reinterpret_cast<const float4*>(ln3_b + L*128 + c0);
            #pragma unroll
            for (int n = 0; n < NJ; n++) {
                float mu, inv;
                row_stats4(x[n][0], x[n][1], x[n][2], x[n][3], mu, inv);
                float4 o;
                o.x = fmaf((x[n][0]-mu)*inv, w3.x, b3.x);
                o.y = fmaf((x[n][1]-mu)*inv, w3.y, b3.y);
                o.z = fmaf((x[n][2]-mu)*inv, w3.z, b3.z);
                o.w = fmaf((x[n][3]-mu)*inv, w3.w, b3.w);
                *reinterpret_cast<float4*>(jn + n*128 + c0) = o;
            }
        }
        float ha[NJ][2];
        {
            float2 fb = *reinterpret_cast<const float2*>(fc1_b + L*64 + lane*2);
            #pragma unroll
            for (int n = 0; n < NJ; n++) { ha[n][0] = fb.x; ha[n][1] = fb.y; }
        }
        #pragma unroll 1
        for (int kc = 0; kc < 2; kc++) {
            __syncthreads();
            for (int idx = tid; idx < 4096; idx += NTHR)
                wbuf[idx] = fc1_w[L*8192 + (kc*64 + (idx >> 6))*64 + (idx & 63)];
            __syncthreads();
            #pragma unroll 2
            for (int kk = 0; kk < 64; kk++) {
                float a[NJ];
                #pragma unroll
                for (int n = 0; n < NJ; n++) a[n] = jn[n*128 + kc*64 + kk];
                float2 w = *reinterpret_cast<float2*>(wbuf + kk*64 + lane*2);
                #pragma unroll
                for (int n = 0; n < NJ; n++) {
                    ha[n][0] = fmaf(a[n], w.x, ha[n][0]);
                    ha[n][1] = fmaf(a[n], w.y, ha[n][1]);
                }
            }
        }
        #pragma unroll
        for (int n = 0; n < NJ; n++) {
            float g0 = 0.5f*ha[n][0]*(1.0f + erff(ha[n][0]*0.70710678118654752f));
            float g1 = 0.5f*ha[n][1]*(1.0f + erff(ha[n][1]*0.70710678118654752f));
            *reinterpret_cast<float2*>(rn + n*64 + lane*2) = make_float2(g0, g1);
        }
        __syncwarp();
        #pragma unroll 1
        for (int kc = 0; kc < 2; kc++) {
            __syncthreads();
            for (int idx = tid; idx < 4096; idx += NTHR)
                wbuf[idx] = fc2_w[L*8192 + (kc*32 + (idx >> 7))*128 + (idx & 127)];
            __syncthreads();
            #pragma unroll 2
            for (int kk = 0; kk < 32; kk++) {
                float a[NJ];
                #pragma unroll
                for (int n = 0; n < NJ; n++) a[n] = rn[n*64 + kc*32 + kk];
                float4 w = *reinterpret_cast<float4*>(wbuf + kk*128 + c0);
                #pragma unroll
                for (int n = 0; n < NJ; n++) {
                    x[n][0] = fmaf(a[n], w.x, x[n][0]);
                    x[n][1] = fmaf(a[n], w.y, x[n][1]);
                    x[n][2] = fmaf(a[n], w.z, x[n][2]);
                    x[n][3] = fmaf(a[n], w.w, x[n][3]);
                }
            }
        }
        {
            float4 fb = *reinterpret_cast<const float4*>(fc2_b + L*128 + c0);
            #pragma unroll
            for (int n = 0; n < NJ; n++) {
                x[n][0]+=fb.x; x[n][1]+=fb.y; x[n][2]+=fb.z; x[n][3]+=fb.w;
            }
        }
        __syncwarp();
    } // layers

    if (eb < NB) {
        #pragma unroll
        for (int n = 0; n < NJ; n++)
            *reinterpret_cast<float4*>(out + base + n*128 + c0) =
                make_float4(x[n][0], x[n][1], x[n][2], x[n][3]);
    }
}

extern "C" void kernel_launch(void* const* d_in, const int* in_sizes, int n_in,
                              void* d_out, int out_size) {
    (void)in_sizes; (void)n_in; (void)out_size;
    const float* joint   = (const float*)d_in[0];
    const float* rel     = (const float*)d_in[1];
    const float* Jqkv_w  = (const float*)d_in[2];
    const float* Jqkv_b  = (const float*)d_in[3];
    const float* Iqk_w   = (const float*)d_in[4];
    const float* Iqk_b   = (const float*)d_in[5];
    const float* Iconv_w = (const float*)d_in[6];
    const float* Iconv_b = (const float*)d_in[7];
    const float* proj_w  = (const float*)d_in[8];
    const float* proj_b  = (const float*)d_in[9];
    const float* ln1_w   = (const float*)d_in[10];
    const float* ln1_b   = (const float*)d_in[11];
    const float* ln2_w   = (const float*)d_in[12];
    const float* ln2_b   = (const float*)d_in[13];
    const float* ln3_w   = (const float*)d_in[14];
    const float* ln3_b   = (const float*)d_in[15];
    const float* fc1_w   = (const float*)d_in[16];
    const float* fc1_b   = (const float*)d_in[17];
    const float* fc2_w   = (const float*)d_in[18];
    const float* fc2_b   = (const float*)d_in[19];

    cudaFuncSetAttribute(jr_kernel, cudaFuncAttributeMaxDynamicSharedMemorySize,
                         SMEM_BYTES);
    const int grid = (NB + EPC - 1) / EPC;   // 2341
    jr_kernel<<<grid, NTHR, SMEM_BYTES>>>(
        joint, rel, Jqkv_w, Jqkv_b, Iqk_w, Iqk_b, Iconv_w, Iconv_b,
        proj_w, proj_b, ln1_w, ln1_b, ln2_w, ln2_b, ln3_w, ln3_b,
        fc1_w, fc1_b, fc2_w, fc2_b, (float*)d_out);
}